// round 8
// baseline (speedup 1.0000x reference)
#include <cuda_runtime.h>

#define FULLMASK 0xFFFFFFFFu
#define WARPS_PER_ROW 8

// One 256-thread block per row; each warp owns a 1024-element chunk.
// NO lgamma: cross-chunk D obtained by a block scan of per-warp log-ratio
// totals (each warp computes its chunk total independently once the integer
// count scan gives s_start). Per-lane per-subiter log deltas are computed
// once (pass 1), stashed in smem, replayed in pass 2 for the warp scans +
// outputs. Small live register state throughout (R3/R6 regime).
__global__ void __launch_bounds__(32 * WARPS_PER_ROW, 5)
bbm_kernel(const float* __restrict__ obs,
           const float* __restrict__ alpha1,
           const float* __restrict__ beta1,
           const float* __restrict__ alpha2,
           const float* __restrict__ beta2,
           const float* __restrict__ mixw,
           float* __restrict__ out,
           int B, int T)
{
    const int wid  = threadIdx.x >> 5;
    const int lane = threadIdx.x & 31;
    const int row  = blockIdx.x;

    const unsigned ltmask = (lane == 0) ? 0u : (FULLMASK >> (32 - lane));

    const float a1c = __ldg(alpha1 + row);
    const float b1c = __ldg(beta1  + row);
    const float a2c = __ldg(alpha2 + row);
    const float b2c = __ldg(beta2  + row);
    const float ab1 = a1c + b1c;
    const float ab2 = a2c + b2c;
    const float w   = __ldg(mixw);
    const float omw = 1.0f - w;

    const int chunk = T / WARPS_PER_ROW;   // 1024

    const float4* __restrict__ orow =
        reinterpret_cast<const float4*>(obs + (size_t)row * (size_t)T);

    const size_t NT = (size_t)B * (size_t)T;
    float* o_a1 = out + (size_t)row * (size_t)T;

    __shared__ int   smem_cnt[WARPS_PER_ROW];
    __shared__ float smem_dtot[WARPS_PER_ROW];
    __shared__ float smem_dacc[WARPS_PER_ROW * 8 * 32];  // [wid][it][lane]

    // ---------- Phase 1a: streaming load of chunk, pack bits, count ----------
    unsigned packed = 0;
    const int vbase = wid * (chunk >> 2) + lane;
    #pragma unroll
    for (int i = 0; i < 8; ++i) {
        const float4 v = __ldcs(orow + vbase + i * 32);
        unsigned nib = (unsigned)(v.x > 0.5f)
                     | ((unsigned)(v.y > 0.5f) << 1)
                     | ((unsigned)(v.z > 0.5f) << 2)
                     | ((unsigned)(v.w > 0.5f) << 3);
        packed |= nib << (4 * i);
    }
    const int warpcnt = __reduce_add_sync(FULLMASK, __popc(packed));
    if (lane == 0) smem_cnt[wid] = warpcnt;
    __syncthreads();

    int s_start = 0;
    #pragma unroll
    for (int k = 0; k < WARPS_PER_ROW; ++k)
        if (k < wid) s_start += smem_cnt[k];

    // ---------- integer pre-pass: per-sub-iter per-lane s0, packed 16-bit ----------
    unsigned s0pack[4];
    {
        int s_run = s_start;
        #pragma unroll
        for (int i = 0; i < 8; ++i) {
            const unsigned nib = (packed >> (4 * i)) & 0xF;
            const unsigned m0 = __ballot_sync(FULLMASK, nib & 1u);
            const unsigned m1 = __ballot_sync(FULLMASK, nib & 2u);
            const unsigned m2 = __ballot_sync(FULLMASK, nib & 4u);
            const unsigned m3 = __ballot_sync(FULLMASK, nib & 8u);
            const int lp = __popc(m0 & ltmask) + __popc(m1 & ltmask)
                         + __popc(m2 & ltmask) + __popc(m3 & ltmask);
            const unsigned s0 = (unsigned)(s_run + lp);
            if (i & 1) s0pack[i >> 1] |= s0 << 16;
            else       s0pack[i >> 1]  = s0;
            s_run += __popc(m0) + __popc(m1) + __popc(m2) + __popc(m3);
        }
    }

    const int tchunk = wid * chunk;

    // ---------- Phase 1b: per-lane log deltas -> smem; per-lane running sum ----------
    float lane_sum = 0.0f;
    #pragma unroll
    for (int it = 0; it < 8; ++it) {
        const int s0 = (int)((s0pack[it >> 1] >> ((it & 1) * 16)) & 0xFFFFu);
        const unsigned nib = (packed >> (4 * it)) & 0xF;
        const float t0f = (float)(tchunk + (it << 7) + (lane << 2));
        float cn = 1.0f, cd = 1.0f;
        int ss = s0;
        #pragma unroll
        for (int j = 0; j < 4; ++j) {
            const int bj = (nib >> j) & 1;
            const float tf = t0f + (float)j;
            const float sf = (float)ss;
            const float ff = tf - sf;
            const float xv = bj ? sf  : ff;
            const float c2 = bj ? a2c : b2c;
            const float c1 = bj ? a1c : b1c;
            cn *= (c2 + xv) * (ab1 + tf);
            cd *= (c1 + xv) * (ab2 + tf);
            ss += bj;
        }
        const float dacc = __logf(__fdividef(cn, cd));
        smem_dacc[(wid * 8 + it) * 32 + lane] = dacc;
        lane_sum += dacc;
    }

    // warp total of log deltas via shfl butterfly reduction
    float wtot = lane_sum;
    #pragma unroll
    for (int d = 16; d >= 1; d >>= 1)
        wtot += __shfl_xor_sync(FULLMASK, wtot, d);
    if (lane == 0) smem_dtot[wid] = wtot;
    __syncthreads();

    // ---------- block scan of warp totals -> D_carry for this chunk ----------
    float D_carry = 0.0f;
    #pragma unroll
    for (int k = 0; k < WARPS_PER_ROW; ++k)
        if (k < wid) D_carry += smem_dtot[k];

    // ---------- Phase 2: sequential sub-iterations, outputs ----------
    #pragma unroll
    for (int it = 0; it < 8; ++it) {
        const int s0 = (int)((s0pack[it >> 1] >> ((it & 1) * 16)) & 0xFFFFu);
        const unsigned nib = (packed >> (4 * it)) & 0xF;
        const int   t0  = tchunk + (it << 7) + (lane << 2);
        const float t0f = (float)t0;

        const float dacc = smem_dacc[(wid * 8 + it) * 32 + lane];

        float finc = dacc;
        #pragma unroll
        for (int d = 1; d < 32; d <<= 1) {
            float n = __shfl_up_sync(FULLMASK, finc, d);
            if (lane >= d) finc += n;
        }
        const float Dbase = D_carry + (finc - dacc);
        const float Dtot  = __shfl_sync(FULLMASK, finc, 31);

        const float omwEb = omw * __expf(Dbase);

        // recompute cheap cumprod factors for outputs
        float cn = 1.0f, cd = 1.0f;
        float oa1[4], ob1[4], oa2[4], ob2[4], opm[4];
        int ss = s0;
        #pragma unroll
        for (int j = 0; j < 4; ++j) {
            const int bj = (nib >> j) & 1;
            const float tf = t0f + (float)j;
            const float sf = (float)ss;
            const float ff = tf - sf;
            oa1[j] = a1c + sf;
            ob1[j] = b1c + ff;
            oa2[j] = a2c + sf;
            ob2[j] = b2c + ff;
            const float wn = w * cd;
            opm[j] = __fdividef(wn, fmaf(omwEb, cn, wn));
            const float xv = bj ? sf  : ff;
            const float c2 = bj ? a2c : b2c;
            const float c1 = bj ? a1c : b1c;
            cn *= (c2 + xv) * (ab1 + tf);
            cd *= (c1 + xv) * (ab2 + tf);
            ss += bj;
        }

        float* p = o_a1 + t0;
        __stcs(reinterpret_cast<float4*>(p),          make_float4(oa1[0], oa1[1], oa1[2], oa1[3]));
        __stcs(reinterpret_cast<float4*>(p + NT),     make_float4(ob1[0], ob1[1], ob1[2], ob1[3]));
        __stcs(reinterpret_cast<float4*>(p + 2 * NT), make_float4(oa2[0], oa2[1], oa2[2], oa2[3]));
        __stcs(reinterpret_cast<float4*>(p + 3 * NT), make_float4(ob2[0], ob2[1], ob2[2], ob2[3]));
        __stcs(reinterpret_cast<float4*>(p + 4 * NT), make_float4(opm[0], opm[1], opm[2], opm[3]));

        D_carry += Dtot;
    }
}

extern "C" void kernel_launch(void* const* d_in, const int* in_sizes, int n_in,
                              void* d_out, int out_size)
{
    const float* obs = (const float*)d_in[0];
    const float* a1  = (const float*)d_in[1];
    const float* b1  = (const float*)d_in[2];
    const float* a2  = (const float*)d_in[3];
    const float* b2  = (const float*)d_in[4];
    const float* mw  = (const float*)d_in[5];

    const int B = in_sizes[1];
    const int T = in_sizes[0] / B;

    dim3 block(32 * WARPS_PER_ROW);
    dim3 grid(B);
    bbm_kernel<<<grid, block>>>(obs, a1, b1, a2, b2, mw, (float*)d_out, B, T);
}

// round 9
// speedup vs baseline: 1.5194x; 1.5194x over previous
#include <cuda_runtime.h>

#define FULLMASK 0xFFFFFFFFu
#define WARPS_PER_ROW 8

// R3 structure (the proven fastest shape), register-trimmed and capped to
// 42 regs -> 6 blocks/SM (48 warps, vs 40 at 47 regs). Per-warp chunk of
// 1024 elems, lgamma closed form for the chunk D_base, sequential 8
// sub-iterations with inline ballots, small live state.
__global__ void __launch_bounds__(32 * WARPS_PER_ROW, 6)
bbm_kernel(const float* __restrict__ obs,
           const float* __restrict__ alpha1,
           const float* __restrict__ beta1,
           const float* __restrict__ alpha2,
           const float* __restrict__ beta2,
           const float* __restrict__ mixw,
           float* __restrict__ out,
           int B, int T)
{
    const int wid  = threadIdx.x >> 5;
    const int lane = threadIdx.x & 31;
    const int row  = blockIdx.x;

    const unsigned ltmask = (lane == 0) ? 0u : (FULLMASK >> (32 - lane));

    const float a1c = __ldg(alpha1 + row);
    const float b1c = __ldg(beta1  + row);
    const float a2c = __ldg(alpha2 + row);
    const float b2c = __ldg(beta2  + row);
    const float ab1 = a1c + b1c;
    const float ab2 = a2c + b2c;
    const float w   = __ldg(mixw);
    const float omw = 1.0f - w;

    const int chunk = T / WARPS_PER_ROW;   // 1024

    const float4* __restrict__ orow =
        reinterpret_cast<const float4*>(obs + (size_t)row * (size_t)T);

    const size_t NT = (size_t)B * (size_t)T;
    float* o_a1 = out + (size_t)row * (size_t)T;

    __shared__ int smem_cnt[WARPS_PER_ROW];

    // ---------- Phase 1: streaming load of chunk, pack bits, count ----------
    unsigned packed = 0;
    const int vbase = wid * (chunk >> 2) + lane;
    #pragma unroll
    for (int i = 0; i < 8; ++i) {
        const float4 v = __ldcs(orow + vbase + i * 32);
        unsigned nib = (unsigned)(v.x > 0.5f)
                     | ((unsigned)(v.y > 0.5f) << 1)
                     | ((unsigned)(v.z > 0.5f) << 2)
                     | ((unsigned)(v.w > 0.5f) << 3);
        packed |= nib << (4 * i);
    }
    const int warpcnt = __reduce_add_sync(FULLMASK, __popc(packed));
    if (lane == 0) smem_cnt[wid] = warpcnt;
    __syncthreads();

    int s_start = 0;
    #pragma unroll
    for (int k = 0; k < WARPS_PER_ROW; ++k)
        if (k < wid) s_start += smem_cnt[k];

    // ---------- chunk D_base via lgamma closed form ----------
    float D_carry = 0.0f;
    if (wid != 0) {
        const float tf = (float)(wid * chunk);
        const float sf = (float)s_start;
        const float ff = tf - sf;
        const float d2 = (lgammaf(a2c + sf) + lgammaf(b2c + ff) - lgammaf(ab2 + tf))
                       - (lgammaf(a2c) + lgammaf(b2c) - lgammaf(ab2));
        const float d1 = (lgammaf(a1c + sf) + lgammaf(b1c + ff) - lgammaf(ab1 + tf))
                       - (lgammaf(a1c) + lgammaf(b1c) - lgammaf(ab1));
        D_carry = d2 - d1;
    }
    int s_carry = s_start;

    const int tchunk = wid * chunk;

    // ---------- Phase 2: sequential sub-iterations (small live state) ----------
    #pragma unroll
    for (int it = 0; it < 8; ++it) {
        const unsigned nib = (packed >> (4 * it)) & 0xF;

        const unsigned m0 = __ballot_sync(FULLMASK, nib & 1u);
        const unsigned m1 = __ballot_sync(FULLMASK, nib & 2u);
        const unsigned m2 = __ballot_sync(FULLMASK, nib & 4u);
        const unsigned m3 = __ballot_sync(FULLMASK, nib & 8u);
        const int s0 = s_carry + __popc(m0 & ltmask) + __popc(m1 & ltmask)
                               + __popc(m2 & ltmask) + __popc(m3 & ltmask);
        const int cntTot = __popc(m0) + __popc(m1) + __popc(m2) + __popc(m3);

        const int   t0  = tchunk + (it << 7) + (lane << 2);
        const float t0f = (float)t0;

        // exclusive cumulative products of per-element ratio factors
        float cnex[4], cdex[4];
        float cn = 1.0f, cd = 1.0f;
        int ss = s0;
        #pragma unroll
        for (int j = 0; j < 4; ++j) {
            cnex[j] = cn;
            cdex[j] = cd;
            const int bj = (nib >> j) & 1;
            const float tf = t0f + (float)j;
            const float sf = (float)ss;
            const float ff = tf - sf;
            const float xv = bj ? sf  : ff;
            const float c2 = bj ? a2c : b2c;
            const float c1 = bj ? a1c : b1c;
            cn *= (c2 + xv) * (ab1 + tf);
            cd *= (c1 + xv) * (ab2 + tf);
            ss += bj;
        }

        const float dacc = __logf(__fdividef(cn, cd));

        float finc = dacc;
        #pragma unroll
        for (int d = 1; d < 32; d <<= 1) {
            float n = __shfl_up_sync(FULLMASK, finc, d);
            if (lane >= d) finc += n;
        }
        const float Dbase = D_carry + (finc - dacc);
        const float Dtot  = __shfl_sync(FULLMASK, finc, 31);

        const float omwEb = omw * __expf(Dbase);

        // outputs: recompute sf from s0 + bits, one div per element
        float o0[4], o1[4], o2[4], o3[4], o4[4];
        ss = s0;
        #pragma unroll
        for (int j = 0; j < 4; ++j) {
            const float tf = t0f + (float)j;
            const float sf = (float)ss;
            const float ff = tf - sf;
            o0[j] = a1c + sf;
            o1[j] = b1c + ff;
            o2[j] = a2c + sf;
            o3[j] = b2c + ff;
            const float wn = w * cdex[j];
            o4[j] = __fdividef(wn, fmaf(omwEb, cnex[j], wn));
            ss += (nib >> j) & 1;
        }

        float* p = o_a1 + t0;
        __stcs(reinterpret_cast<float4*>(p),          make_float4(o0[0], o0[1], o0[2], o0[3]));
        __stcs(reinterpret_cast<float4*>(p + NT),     make_float4(o1[0], o1[1], o1[2], o1[3]));
        __stcs(reinterpret_cast<float4*>(p + 2 * NT), make_float4(o2[0], o2[1], o2[2], o2[3]));
        __stcs(reinterpret_cast<float4*>(p + 3 * NT), make_float4(o3[0], o3[1], o3[2], o3[3]));
        __stcs(reinterpret_cast<float4*>(p + 4 * NT), make_float4(o4[0], o4[1], o4[2], o4[3]));

        s_carry += cntTot;
        D_carry += Dtot;
    }
}

extern "C" void kernel_launch(void* const* d_in, const int* in_sizes, int n_in,
                              void* d_out, int out_size)
{
    const float* obs = (const float*)d_in[0];
    const float* a1  = (const float*)d_in[1];
    const float* b1  = (const float*)d_in[2];
    const float* a2  = (const float*)d_in[3];
    const float* b2  = (const float*)d_in[4];
    const float* mw  = (const float*)d_in[5];

    const int B = in_sizes[1];
    const int T = in_sizes[0] / B;

    dim3 block(32 * WARPS_PER_ROW);
    dim3 grid(B);
    bbm_kernel<<<grid, block>>>(obs, a1, b1, a2, b2, mw, (float*)d_out, B, T);
}

// round 10
// speedup vs baseline: 1.6789x; 1.1049x over previous
#include <cuda_runtime.h>

#define FULLMASK 0xFFFFFFFFu
#define WARPS_PER_ROW 8

// Best-known configuration (R3, 127.5us): one 256-thread block per row;
// each warp owns a 1024-element chunk. Phase 1: packed read + block count
// scan -> s_start; chunk D_base via lgamma closed form. Phase 2: 8
// sequential sub-iterations (128 elems each) with small live state:
// ballot prefix, FMA-pipe cumprods, 1 log + 1 exp per lane per sub-iter,
// 1 fast-div per element. Natural register allocation (47 regs, 5 blocks/SM)
// — every forced cap (R4: 40 on big state, R9: 42) and every restructure
// (R5 wide-ILP, R6 cache hints, R8 smem two-pass) measured worse.
__global__ void __launch_bounds__(32 * WARPS_PER_ROW)
bbm_kernel(const float* __restrict__ obs,
           const float* __restrict__ alpha1,
           const float* __restrict__ beta1,
           const float* __restrict__ alpha2,
           const float* __restrict__ beta2,
           const float* __restrict__ mixw,
           float* __restrict__ out,
           int B, int T)
{
    const int wid  = threadIdx.x >> 5;
    const int lane = threadIdx.x & 31;
    const int row  = blockIdx.x;

    const unsigned ltmask = (lane == 0) ? 0u : (FULLMASK >> (32 - lane));

    const float a1c = __ldg(alpha1 + row);
    const float b1c = __ldg(beta1  + row);
    const float a2c = __ldg(alpha2 + row);
    const float b2c = __ldg(beta2  + row);
    const float ab1 = a1c + b1c;
    const float ab2 = a2c + b2c;
    const float w   = __ldg(mixw);
    const float omw = 1.0f - w;

    const int chunk    = T / WARPS_PER_ROW;   // 1024
    const int subiters = chunk >> 7;          // 8

    const float4* __restrict__ orow =
        reinterpret_cast<const float4*>(obs + (size_t)row * (size_t)T);

    const size_t NT = (size_t)B * (size_t)T;
    float* o_a1 = out + (size_t)row * (size_t)T;
    float* o_b1 = o_a1 + NT;
    float* o_a2 = o_b1 + NT;
    float* o_b2 = o_a2 + NT;
    float* o_pm = o_b2 + NT;

    __shared__ int smem_cnt[WARPS_PER_ROW];

    // ---------- Phase 1: load chunk, pack bits, count ----------
    unsigned packed = 0;
    const int vbase = wid * (chunk >> 2) + lane;
    #pragma unroll
    for (int i = 0; i < 8; ++i) {
        const float4 v = orow[vbase + i * 32];
        unsigned nib = (unsigned)(v.x > 0.5f)
                     | ((unsigned)(v.y > 0.5f) << 1)
                     | ((unsigned)(v.z > 0.5f) << 2)
                     | ((unsigned)(v.w > 0.5f) << 3);
        packed |= nib << (4 * i);
    }
    const int warpcnt = __reduce_add_sync(FULLMASK, __popc(packed));
    if (lane == 0) smem_cnt[wid] = warpcnt;
    __syncthreads();

    int s_start = 0;
    #pragma unroll
    for (int k = 0; k < WARPS_PER_ROW; ++k)
        if (k < wid) s_start += smem_cnt[k];

    // ---------- D_base for this chunk via lgamma closed form ----------
    float D_carry = 0.0f;
    if (wid != 0) {
        const float tf = (float)(wid * chunk);
        const float sf = (float)s_start;
        const float ff = tf - sf;
        const float d2 = (lgammaf(a2c + sf) + lgammaf(b2c + ff) - lgammaf(ab2 + tf))
                       - (lgammaf(a2c) + lgammaf(b2c) - lgammaf(ab2));
        const float d1 = (lgammaf(a1c + sf) + lgammaf(b1c + ff) - lgammaf(ab1 + tf))
                       - (lgammaf(a1c) + lgammaf(b1c) - lgammaf(ab1));
        D_carry = d2 - d1;
    }
    int s_carry = s_start;

    // ---------- Phase 2: local recurrence over 8 sub-iterations ----------
    for (int it = 0; it < subiters; ++it) {
        const unsigned nib = (packed >> (4 * it)) & 0xF;
        const int b0 = (nib)      & 1;
        const int b1 = (nib >> 1) & 1;
        const int b2 = (nib >> 2) & 1;
        const int b3 = (nib >> 3) & 1;

        const unsigned m0 = __ballot_sync(FULLMASK, b0);
        const unsigned m1 = __ballot_sync(FULLMASK, b1);
        const unsigned m2 = __ballot_sync(FULLMASK, b2);
        const unsigned m3 = __ballot_sync(FULLMASK, b3);
        const int s0 = s_carry + __popc(m0 & ltmask) + __popc(m1 & ltmask)
                               + __popc(m2 & ltmask) + __popc(m3 & ltmask);
        const int cntTot = __popc(m0) + __popc(m1) + __popc(m2) + __popc(m3);

        const int   t0  = wid * chunk + (it << 7) + (lane << 2);
        const float t0f = (float)t0;

        // per-element ratio factors; exclusive cumulative products
        int bj[4] = {b0, b1, b2, b3};
        float sfv[4], num[4], den[4];
        int ss = s0;
        #pragma unroll
        for (int j = 0; j < 4; ++j) {
            const float tf = t0f + (float)j;
            const float sf = (float)ss;
            const float ff = tf - sf;
            sfv[j] = sf;
            const float xv = bj[j] ? sf  : ff;
            const float c2 = bj[j] ? a2c : b2c;
            const float c1 = bj[j] ? a1c : b1c;
            num[j] = (c2 + xv) * (ab1 + tf);
            den[j] = (c1 + xv) * (ab2 + tf);
            ss += bj[j];
        }
        float cnex[4], cdex[4];
        cnex[0] = 1.0f;             cdex[0] = 1.0f;
        cnex[1] = num[0];           cdex[1] = den[0];
        cnex[2] = cnex[1] * num[1]; cdex[2] = cdex[1] * den[1];
        cnex[3] = cnex[2] * num[2]; cdex[3] = cdex[2] * den[2];
        const float cnInc = cnex[3] * num[3];
        const float cdInc = cdex[3] * den[3];

        const float dacc = __logf(__fdividef(cnInc, cdInc));

        float finc = dacc;
        #pragma unroll
        for (int d = 1; d < 32; d <<= 1) {
            float n = __shfl_up_sync(FULLMASK, finc, d);
            if (lane >= d) finc += n;
        }
        const float Dbase = D_carry + (finc - dacc);
        const float Dtot  = __shfl_sync(FULLMASK, finc, 31);

        const float omwEb = omw * __expf(Dbase);

        float oa1[4], ob1[4], oa2[4], ob2[4], opm[4];
        #pragma unroll
        for (int j = 0; j < 4; ++j) {
            const float tf = t0f + (float)j;
            const float sf = sfv[j];
            const float ff = tf - sf;
            oa1[j] = a1c + sf;
            ob1[j] = b1c + ff;
            oa2[j] = a2c + sf;
            ob2[j] = b2c + ff;
            const float wn = w * cdex[j];
            opm[j] = __fdividef(wn, fmaf(omwEb, cnex[j], wn));
        }

        *reinterpret_cast<float4*>(o_a1 + t0) = make_float4(oa1[0], oa1[1], oa1[2], oa1[3]);
        *reinterpret_cast<float4*>(o_b1 + t0) = make_float4(ob1[0], ob1[1], ob1[2], ob1[3]);
        *reinterpret_cast<float4*>(o_a2 + t0) = make_float4(oa2[0], oa2[1], oa2[2], oa2[3]);
        *reinterpret_cast<float4*>(o_b2 + t0) = make_float4(ob2[0], ob2[1], ob2[2], ob2[3]);
        *reinterpret_cast<float4*>(o_pm + t0) = make_float4(opm[0], opm[1], opm[2], opm[3]);

        s_carry += cntTot;
        D_carry += Dtot;
    }
}

extern "C" void kernel_launch(void* const* d_in, const int* in_sizes, int n_in,
                              void* d_out, int out_size)
{
    const float* obs = (const float*)d_in[0];
    const float* a1  = (const float*)d_in[1];
    const float* b1  = (const float*)d_in[2];
    const float* a2  = (const float*)d_in[3];
    const float* b2  = (const float*)d_in[4];
    const float* mw  = (const float*)d_in[5];

    const int B = in_sizes[1];
    const int T = in_sizes[0] / B;

    dim3 block(32 * WARPS_PER_ROW);
    dim3 grid(B);
    bbm_kernel<<<grid, block>>>(obs, a1, b1, a2, b2, mw, (float*)d_out, B, T);
}